// round 1
// baseline (speedup 1.0000x reference)
#include <cuda_runtime.h>

typedef unsigned long long u64;

#define DOC_L 5
#define HID   100
#define NB    8                 // batches per CTA
#define ROWS  (NB * DOC_L)      // 40
#define PAD   102               // smem row stride (floats): conflict-free + float2 aligned
#define NT    128

// ---------------- packed f32x2 helpers (FFMA2 is PTX-only) ----------------
__device__ __forceinline__ u64 fma2(u64 a, u64 b, u64 c) {
    u64 d;
    asm("fma.rn.f32x2 %0, %1, %2, %3;" : "=l"(d) : "l"(a), "l"(b), "l"(c));
    return d;
}
__device__ __forceinline__ u64 dup2(float a) {
    u64 d;
    asm("mov.b64 %0, {%1, %1};" : "=l"(d) : "f"(a));
    return d;
}
__device__ __forceinline__ void unpack2(u64 v, float& x, float& y) {
    asm("mov.b64 {%0, %1}, %2;" : "=f"(x), "=f"(y) : "l"(v));
}
__device__ __forceinline__ u64 ldw2(const float* p) {
    return *reinterpret_cast<const u64*>(p);   // 8B-aligned weight pair
}
__device__ __forceinline__ float tanh_fast(float x) {
    // 1 - 2/(e^{2x}+1); exact at +-inf, ~1e-6 rel err
    return 1.f - 2.f / (__expf(2.f * x) + 1.f);
}
__device__ __forceinline__ float sigmoid_fast(float x) {
    return 1.f / (1.f + __expf(-x));
}

__global__ __launch_bounds__(NT)
void reading_memory_kernel(const float* __restrict__ sub_emb,
                           const float* __restrict__ memory,
                           const int*   __restrict__ sub_len,
                           const float* __restrict__ sub_raw,
                           const float* __restrict__ W_mem,
                           const float* __restrict__ b_mem,
                           const float* __restrict__ W_sub,
                           const float* __restrict__ b_sub,
                           const float* __restrict__ W_gate,
                           const float* __restrict__ b_gate,
                           float* __restrict__ out)
{
    extern __shared__ float s_base[];
    float* s_mem = s_base;                    // [ROWS][PAD] memory
    float* s_se  = s_mem + ROWS * PAD;        // [ROWS][PAD] sub_emb
    float* s_raw = s_se  + ROWS * PAD;        // [ROWS][PAD] sub_emb_raw
    float* s_s4a = s_raw + ROWS * PAD;        // [ROWS][PAD] sub_4att
    float* s_m4a = s_s4a + ROWS * PAD;        // [ROWS][PAD] mem_4att, reused as sub_mem
    float* s_att = s_m4a + ROWS * PAD;        // [NB][5][5]
    int*   s_len = (int*)(s_att + NB * DOC_L * DOC_L);

    const int tid = threadIdx.x;
    const int b0  = blockIdx.x * NB;

    const float* g_mem = memory  + (size_t)b0 * DOC_L * HID;
    const float* g_se  = sub_emb + (size_t)b0 * DOC_L * HID;
    const float* g_raw = sub_raw + (size_t)b0 * DOC_L * HID;

    // ---- stage inputs (HID=100 divisible by 4; rows never straddle a float4) ----
    for (int i = tid; i < ROWS * HID / 4; i += NT) {
        int e = i * 4;
        int r = e / HID;
        int c = e - r * HID;
        float* dm = s_mem + r * PAD + c;
        float* ds = s_se  + r * PAD + c;
        float* dr = s_raw + r * PAD + c;
        float4 vm = *(const float4*)(g_mem + e);
        float4 vs = *(const float4*)(g_se  + e);
        float4 vr = *(const float4*)(g_raw + e);
        dm[0] = vm.x; dm[1] = vm.y; dm[2] = vm.z; dm[3] = vm.w;
        ds[0] = vs.x; ds[1] = vs.y; ds[2] = vs.z; ds[3] = vs.w;
        dr[0] = vr.x; dr[1] = vr.y; dr[2] = vr.z; dr[3] = vr.w;
    }
    if (tid < NB) s_len[tid] = sub_len[b0 + tid];
    __syncthreads();

    const int  hq     = tid % 25;        // h-quad index: owns h = 4*hq .. 4*hq+3
    const int  rg     = tid / 25;        // row-group 0..4 (tid>=125 idle in GEMM phases)
    const bool active = (tid < 125);
    const int  col    = 4 * hq;
    const int  r0     = rg * 8;

    // ---------------- phase A: mem_4att = tanh(memory @ W_mem + b_mem) ----------------
    if (active) {
        u64 a0[8], a1[8];
        u64 bb0 = ldw2(b_mem + col), bb1 = ldw2(b_mem + col + 2);
        #pragma unroll
        for (int i = 0; i < 8; i++) { a0[i] = bb0; a1[i] = bb1; }
        #pragma unroll 2
        for (int j = 0; j < HID; j += 2) {
            u64 w00 = ldw2(W_mem + j * HID + col);
            u64 w01 = ldw2(W_mem + j * HID + col + 2);
            u64 w10 = ldw2(W_mem + (j + 1) * HID + col);
            u64 w11 = ldw2(W_mem + (j + 1) * HID + col + 2);
            #pragma unroll
            for (int i = 0; i < 8; i++) {
                float2 av = *(const float2*)(s_mem + (r0 + i) * PAD + j);
                u64 ax = dup2(av.x), ay = dup2(av.y);
                a0[i] = fma2(ax, w00, a0[i]);
                a1[i] = fma2(ax, w01, a1[i]);
                a0[i] = fma2(ay, w10, a0[i]);
                a1[i] = fma2(ay, w11, a1[i]);
            }
        }
        #pragma unroll
        for (int i = 0; i < 8; i++) {
            float x0, x1, x2, x3;
            unpack2(a0[i], x0, x1);
            unpack2(a1[i], x2, x3);
            float* d = s_m4a + (r0 + i) * PAD + col;
            d[0] = tanh_fast(x0); d[1] = tanh_fast(x1);
            d[2] = tanh_fast(x2); d[3] = tanh_fast(x3);
        }
    }

    // ---------------- phase A2: sub_4att = tanh(cat(sub_emb, sub_raw) @ W_sub + b_sub) ----------------
    if (active) {
        u64 a0[8], a1[8];
        u64 bb0 = ldw2(b_sub + col), bb1 = ldw2(b_sub + col + 2);
        #pragma unroll
        for (int i = 0; i < 8; i++) { a0[i] = bb0; a1[i] = bb1; }
        // first half: sub_emb with W_sub rows [0, 100)
        #pragma unroll 2
        for (int j = 0; j < HID; j += 2) {
            u64 w00 = ldw2(W_sub + j * HID + col);
            u64 w01 = ldw2(W_sub + j * HID + col + 2);
            u64 w10 = ldw2(W_sub + (j + 1) * HID + col);
            u64 w11 = ldw2(W_sub + (j + 1) * HID + col + 2);
            #pragma unroll
            for (int i = 0; i < 8; i++) {
                float2 av = *(const float2*)(s_se + (r0 + i) * PAD + j);
                u64 ax = dup2(av.x), ay = dup2(av.y);
                a0[i] = fma2(ax, w00, a0[i]);
                a1[i] = fma2(ax, w01, a1[i]);
                a0[i] = fma2(ay, w10, a0[i]);
                a1[i] = fma2(ay, w11, a1[i]);
            }
        }
        // second half: sub_emb_raw with W_sub rows [100, 200)
        #pragma unroll 2
        for (int j = 0; j < HID; j += 2) {
            const float* wr = W_sub + (HID + j) * HID + col;
            u64 w00 = ldw2(wr);
            u64 w01 = ldw2(wr + 2);
            u64 w10 = ldw2(wr + HID);
            u64 w11 = ldw2(wr + HID + 2);
            #pragma unroll
            for (int i = 0; i < 8; i++) {
                float2 av = *(const float2*)(s_raw + (r0 + i) * PAD + j);
                u64 ax = dup2(av.x), ay = dup2(av.y);
                a0[i] = fma2(ax, w00, a0[i]);
                a1[i] = fma2(ax, w01, a1[i]);
                a0[i] = fma2(ay, w10, a0[i]);
                a1[i] = fma2(ay, w11, a1[i]);
            }
        }
        #pragma unroll
        for (int i = 0; i < 8; i++) {
            float x0, x1, x2, x3;
            unpack2(a0[i], x0, x1);
            unpack2(a1[i], x2, x3);
            float* d = s_s4a + (r0 + i) * PAD + col;
            d[0] = tanh_fast(x0); d[1] = tanh_fast(x1);
            d[2] = tanh_fast(x2); d[3] = tanh_fast(x3);
        }
    }
    __syncthreads();

    // ---------------- phase B: attention scores ----------------
    for (int p = tid; p < NB * 25; p += NT) {
        int b   = p / 25;
        int rem = p - b * 25;
        int q   = rem / 5;
        int k   = rem - q * 5;
        const float* x = s_s4a + (b * DOC_L + q) * PAD;
        const float* y = s_m4a + (b * DOC_L + k) * PAD;
        float s = 0.f;
        #pragma unroll
        for (int j = 0; j < HID; j += 2) {
            float2 xv = *(const float2*)(x + j);
            float2 yv = *(const float2*)(y + j);
            s = fmaf(xv.x, yv.x, s);
            s = fmaf(xv.y, yv.y, s);
        }
        s_att[p] = s;
    }
    __syncthreads();

    // softmax per (b, q) row; invalid query rows -> all-zero attention
    if (tid < NB * DOC_L) {
        int b = tid / DOC_L;
        int q = tid - b * DOC_L;
        float* a = s_att + b * 25 + q * 5;
        if (q < s_len[b]) {
            float m = a[0];
            #pragma unroll
            for (int k = 1; k < 5; k++) m = fmaxf(m, a[k]);
            float e[5], s = 0.f;
            #pragma unroll
            for (int k = 0; k < 5; k++) { e[k] = __expf(a[k] - m); s += e[k]; }
            float inv = 1.f / s;
            #pragma unroll
            for (int k = 0; k < 5; k++) a[k] = e[k] * inv;
        } else {
            #pragma unroll
            for (int k = 0; k < 5; k++) a[k] = 0.f;
        }
    }
    __syncthreads();

    // ---------------- sub_mem = att @ memory (overwrites s_m4a) ----------------
    for (int idx = tid; idx < ROWS * HID; idx += NT) {
        int r = idx / HID;
        int h = idx - r * HID;
        int b = r / DOC_L;
        int q = r - b * DOC_L;
        const float* a    = s_att + b * 25 + q * 5;
        const float* mrow = s_mem + b * DOC_L * PAD + h;
        float v = a[0] * mrow[0];
        v = fmaf(a[1], mrow[PAD],     v);
        v = fmaf(a[2], mrow[2 * PAD], v);
        v = fmaf(a[3], mrow[3 * PAD], v);
        v = fmaf(a[4], mrow[4 * PAD], v);
        s_m4a[r * PAD + h] = v;
    }
    __syncthreads();

    // ---------------- phase C: gate GEMM (K=300) + output ----------------
    if (active) {
        u64 a0[8], a1[8];
        u64 bb0 = ldw2(b_gate + col), bb1 = ldw2(b_gate + col + 2);
        #pragma unroll
        for (int i = 0; i < 8; i++) { a0[i] = bb0; a1[i] = bb1; }
        #pragma unroll 2
        for (int j = 0; j < HID; j++) {
            const float* wg = W_gate + j * HID + col;
            u64 wa0 = ldw2(wg);
            u64 wa1 = ldw2(wg + 2);
            u64 wb0 = ldw2(wg + HID * HID);
            u64 wb1 = ldw2(wg + HID * HID + 2);
            u64 wc0 = ldw2(wg + 2 * HID * HID);
            u64 wc1 = ldw2(wg + 2 * HID * HID + 2);
            #pragma unroll
            for (int i = 0; i < 8; i++) {
                float vse = s_se [(r0 + i) * PAD + j];
                float vsm = s_m4a[(r0 + i) * PAD + j];
                float vpr = vse * vsm;
                u64 d;
                d = dup2(vse); a0[i] = fma2(d, wa0, a0[i]); a1[i] = fma2(d, wa1, a1[i]);
                d = dup2(vsm); a0[i] = fma2(d, wb0, a0[i]); a1[i] = fma2(d, wb1, a1[i]);
                d = dup2(vpr); a0[i] = fma2(d, wc0, a0[i]); a1[i] = fma2(d, wc1, a1[i]);
            }
        }
        #pragma unroll
        for (int i = 0; i < 8; i++) {
            int r = r0 + i;
            float x0, x1, x2, x3;
            unpack2(a0[i], x0, x1);
            unpack2(a1[i], x2, x3);
            const float* pse = s_se  + r * PAD + col;
            const float* psm = s_m4a + r * PAD + col;
            float4 o;
            {
                float g = sigmoid_fast(x0); o.x = pse[0] + g * (psm[0] - pse[0]);
            }
            {
                float g = sigmoid_fast(x1); o.y = pse[1] + g * (psm[1] - pse[1]);
            }
            {
                float g = sigmoid_fast(x2); o.z = pse[2] + g * (psm[2] - pse[2]);
            }
            {
                float g = sigmoid_fast(x3); o.w = pse[3] + g * (psm[3] - pse[3]);
            }
            *(float4*)(out + (size_t)(b0 * DOC_L + r) * HID + col) = o;
        }
    }
}

extern "C" void kernel_launch(void* const* d_in, const int* in_sizes, int n_in,
                              void* d_out, int out_size)
{
    const float* sub_emb = (const float*)d_in[0];
    const float* memory  = (const float*)d_in[1];
    const int*   sub_len = (const int*)  d_in[2];
    const float* sub_raw = (const float*)d_in[3];
    const float* W_mem   = (const float*)d_in[4];
    const float* b_mem   = (const float*)d_in[5];
    const float* W_sub   = (const float*)d_in[6];
    const float* b_sub   = (const float*)d_in[7];
    const float* W_gate  = (const float*)d_in[8];
    const float* b_gate  = (const float*)d_in[9];
    float* out = (float*)d_out;

    const int B = in_sizes[2];                 // 65536
    const int smem_bytes = (5 * ROWS * PAD + NB * DOC_L * DOC_L + NB) * 4;

    cudaFuncSetAttribute(reading_memory_kernel,
                         cudaFuncAttributeMaxDynamicSharedMemorySize, smem_bytes);

    dim3 grid(B / NB);
    reading_memory_kernel<<<grid, NT, smem_bytes>>>(
        sub_emb, memory, sub_len, sub_raw,
        W_mem, b_mem, W_sub, b_sub, W_gate, b_gate, out);
}

// round 6
// speedup vs baseline: 1.4578x; 1.4578x over previous
#include <cuda_runtime.h>

typedef unsigned long long u64;

#define DOC_L 5
#define HID   100
#define NB    8                 // batches per CTA
#define ROWS  (NB * DOC_L)      // 40
#define S     42                // transposed smem row stride (floats), even for LDS.64
#define NT    128

// ---------------- packed f32x2 helpers ----------------
__device__ __forceinline__ u64 fma2(u64 a, u64 b, u64 c) {
    u64 d;
    asm("fma.rn.f32x2 %0, %1, %2, %3;" : "=l"(d) : "l"(a), "l"(b), "l"(c));
    return d;
}
__device__ __forceinline__ u64 mul2(u64 a, u64 b) {
    u64 d;
    asm("mul.rn.f32x2 %0, %1, %2;" : "=l"(d) : "l"(a), "l"(b));
    return d;
}
__device__ __forceinline__ u64 dup2(float a) {
    u64 d;
    asm("mov.b64 %0, {%1, %1};" : "=l"(d) : "f"(a));
    return d;
}
__device__ __forceinline__ void unpack2(u64 v, float& x, float& y) {
    asm("mov.b64 {%0, %1}, %2;" : "=f"(x), "=f"(y) : "l"(v));
}
__device__ __forceinline__ float tanh_fast(float x) {
    return 1.f - 2.f / (__expf(2.f * x) + 1.f);
}
__device__ __forceinline__ float sigmoid_fast(float x) {
    return 1.f / (1.f + __expf(-x));
}

__global__ __launch_bounds__(NT)
void reading_memory_kernel(const float* __restrict__ sub_emb,
                           const float* __restrict__ memory,
                           const int*   __restrict__ sub_len,
                           const float* __restrict__ sub_raw,
                           const float* __restrict__ W_mem,
                           const float* __restrict__ b_mem,
                           const float* __restrict__ W_sub,
                           const float* __restrict__ b_sub,
                           const float* __restrict__ W_gate,
                           const float* __restrict__ b_gate,
                           float* __restrict__ out)
{
    extern __shared__ float sm[];
    // all activations stored TRANSPOSED: array[h][row], stride S
    float* t_mem = sm;                  // memory
    float* t_se  = t_mem + HID * S;     // sub_emb
    float* t_raw = t_se  + HID * S;     // sub_emb_raw; ALIASED: becomes sub_4att after A2
    float* t_s4a = t_raw;               // sub_4att (overlays t_raw; barrier-protected)
    float* t_m4a = t_raw + HID * S;     // mem_4att, later sub_mem
    float* s_att = t_m4a + HID * S;     // [NB][5][5]
    int*   s_len = (int*)(s_att + NB * DOC_L * DOC_L);

    const int tid = threadIdx.x;
    const int b0  = blockIdx.x * NB;

    const float* g_mem = memory  + (size_t)b0 * DOC_L * HID;
    const float* g_se  = sub_emb + (size_t)b0 * DOC_L * HID;
    const float* g_raw = sub_raw + (size_t)b0 * DOC_L * HID;

    // ---- stage inputs transposed: read float4 of a row, scatter to 4 h-rows ----
    for (int i = tid; i < ROWS * HID / 4; i += NT) {
        int e = i * 4;
        int r = e / HID;
        int c = e - r * HID;
        float4 vm = *(const float4*)(g_mem + e);
        float4 vs = *(const float4*)(g_se  + e);
        float4 vr = *(const float4*)(g_raw + e);
        t_mem[(c + 0) * S + r] = vm.x; t_mem[(c + 1) * S + r] = vm.y;
        t_mem[(c + 2) * S + r] = vm.z; t_mem[(c + 3) * S + r] = vm.w;
        t_se [(c + 0) * S + r] = vs.x; t_se [(c + 1) * S + r] = vs.y;
        t_se [(c + 2) * S + r] = vs.z; t_se [(c + 3) * S + r] = vs.w;
        t_raw[(c + 0) * S + r] = vr.x; t_raw[(c + 1) * S + r] = vr.y;
        t_raw[(c + 2) * S + r] = vr.z; t_raw[(c + 3) * S + r] = vr.w;
    }
    if (tid < NB) s_len[tid] = sub_len[b0 + tid];
    __syncthreads();

    const int  hq     = tid % 25;       // owns cols col..col+3
    const int  rg     = tid / 25;       // row group (8 rows = 4 row-pairs)
    const bool active = (tid < 125);
    const int  col    = 4 * hq;
    const int  rbase  = rg * 8;

    // ================= phase A: mem_4att = tanh(memory @ W_mem + b) =================
    if (active) {
        u64 acc[4][4];                  // [row-pair][h]
        float4 bb = *(const float4*)(b_mem + col);
        {
            u64 b0d = dup2(bb.x), b1d = dup2(bb.y), b2d = dup2(bb.z), b3d = dup2(bb.w);
            #pragma unroll
            for (int rp = 0; rp < 4; rp++) {
                acc[rp][0] = b0d; acc[rp][1] = b1d; acc[rp][2] = b2d; acc[rp][3] = b3d;
            }
        }
        #pragma unroll 2
        for (int j = 0; j < HID; j++) {
            float4 w = __ldg((const float4*)(W_mem + j * HID + col));
            u64 w0 = dup2(w.x), w1 = dup2(w.y), w2 = dup2(w.z), w3 = dup2(w.w);
            const float* arow = t_mem + j * S + rbase;
            #pragma unroll
            for (int rp = 0; rp < 4; rp++) {
                u64 a = *(const u64*)(arow + 2 * rp);
                acc[rp][0] = fma2(a, w0, acc[rp][0]);
                acc[rp][1] = fma2(a, w1, acc[rp][1]);
                acc[rp][2] = fma2(a, w2, acc[rp][2]);
                acc[rp][3] = fma2(a, w3, acc[rp][3]);
            }
        }
        #pragma unroll
        for (int rp = 0; rp < 4; rp++) {
            #pragma unroll
            for (int h = 0; h < 4; h++) {
                float e, o;
                unpack2(acc[rp][h], e, o);
                float2 v = make_float2(tanh_fast(e), tanh_fast(o));
                *(float2*)(t_m4a + (col + h) * S + rbase + 2 * rp) = v;
            }
        }
    }

    // ========= phase A2: sub_4att = tanh(cat(sub_emb, raw) @ W_sub + b) =========
    // Accumulate first (reads t_se + t_raw), then BARRIER, then write s4a into
    // the t_raw buffer (safe: all raw reads have completed block-wide).
    u64 acc2[4][4];
    if (active) {
        float4 bb = *(const float4*)(b_sub + col);
        {
            u64 b0d = dup2(bb.x), b1d = dup2(bb.y), b2d = dup2(bb.z), b3d = dup2(bb.w);
            #pragma unroll
            for (int rp = 0; rp < 4; rp++) {
                acc2[rp][0] = b0d; acc2[rp][1] = b1d; acc2[rp][2] = b2d; acc2[rp][3] = b3d;
            }
        }
        #pragma unroll 2
        for (int j = 0; j < HID; j++) {
            float4 w = __ldg((const float4*)(W_sub + j * HID + col));
            u64 w0 = dup2(w.x), w1 = dup2(w.y), w2 = dup2(w.z), w3 = dup2(w.w);
            const float* arow = t_se + j * S + rbase;
            #pragma unroll
            for (int rp = 0; rp < 4; rp++) {
                u64 a = *(const u64*)(arow + 2 * rp);
                acc2[rp][0] = fma2(a, w0, acc2[rp][0]);
                acc2[rp][1] = fma2(a, w1, acc2[rp][1]);
                acc2[rp][2] = fma2(a, w2, acc2[rp][2]);
                acc2[rp][3] = fma2(a, w3, acc2[rp][3]);
            }
        }
        #pragma unroll 2
        for (int j = 0; j < HID; j++) {
            float4 w = __ldg((const float4*)(W_sub + (HID + j) * HID + col));
            u64 w0 = dup2(w.x), w1 = dup2(w.y), w2 = dup2(w.z), w3 = dup2(w.w);
            const float* arow = t_raw + j * S + rbase;
            #pragma unroll
            for (int rp = 0; rp < 4; rp++) {
                u64 a = *(const u64*)(arow + 2 * rp);
                acc2[rp][0] = fma2(a, w0, acc2[rp][0]);
                acc2[rp][1] = fma2(a, w1, acc2[rp][1]);
                acc2[rp][2] = fma2(a, w2, acc2[rp][2]);
                acc2[rp][3] = fma2(a, w3, acc2[rp][3]);
            }
        }
    }
    __syncthreads();   // all t_raw reads done block-wide; safe to overwrite with s4a
    if (active) {
        #pragma unroll
        for (int rp = 0; rp < 4; rp++) {
            #pragma unroll
            for (int h = 0; h < 4; h++) {
                float e, o;
                unpack2(acc2[rp][h], e, o);
                float2 v = make_float2(tanh_fast(e), tanh_fast(o));
                *(float2*)(t_s4a + (col + h) * S + rbase + 2 * rp) = v;
            }
        }
    }
    __syncthreads();

    // ================= attention scores =================
    for (int p = tid; p < NB * 25; p += NT) {
        int b   = p / 25;
        int rem = p - b * 25;
        int q   = rem / 5;
        int k   = rem - q * 5;
        int rq  = b * DOC_L + q;
        int rk  = b * DOC_L + k;
        float s = 0.f;
        #pragma unroll 4
        for (int j = 0; j < HID; j++)
            s = fmaf(t_s4a[j * S + rq], t_m4a[j * S + rk], s);
        s_att[p] = s;
    }
    __syncthreads();

    // softmax per (b, q); invalid query rows -> zero attention
    if (tid < NB * DOC_L) {
        int b = tid / DOC_L;
        int q = tid - b * DOC_L;
        float* a = s_att + b * 25 + q * 5;
        if (q < s_len[b]) {
            float m = a[0];
            #pragma unroll
            for (int k = 1; k < 5; k++) m = fmaxf(m, a[k]);
            float e[5], s = 0.f;
            #pragma unroll
            for (int k = 0; k < 5; k++) { e[k] = __expf(a[k] - m); s += e[k]; }
            float inv = 1.f / s;
            #pragma unroll
            for (int k = 0; k < 5; k++) a[k] = e[k] * inv;
        } else {
            #pragma unroll
            for (int k = 0; k < 5; k++) a[k] = 0.f;
        }
    }
    __syncthreads();

    // ---- sub_mem = att @ memory (transposed write; overwrites t_m4a) ----
    for (int idx = tid; idx < HID * ROWS; idx += NT) {
        int h = idx % HID;
        int r = idx / HID;
        int b = r / DOC_L;
        int q = r - b * DOC_L;
        const float* a  = s_att + b * 25 + q * 5;
        const float* mr = t_mem + h * S + b * DOC_L;
        float v = a[0] * mr[0];
        v = fmaf(a[1], mr[1], v);
        v = fmaf(a[2], mr[2], v);
        v = fmaf(a[3], mr[3], v);
        v = fmaf(a[4], mr[4], v);
        t_m4a[h * S + r] = v;
    }
    __syncthreads();

    // ================= gate GEMM (K=300) + output =================
    if (active) {
        u64 acc[4][4];
        float4 bb = *(const float4*)(b_gate + col);
        {
            u64 b0d = dup2(bb.x), b1d = dup2(bb.y), b2d = dup2(bb.z), b3d = dup2(bb.w);
            #pragma unroll
            for (int rp = 0; rp < 4; rp++) {
                acc[rp][0] = b0d; acc[rp][1] = b1d; acc[rp][2] = b2d; acc[rp][3] = b3d;
            }
        }
        #pragma unroll 2
        for (int j = 0; j < HID; j++) {
            const float* wg = W_gate + j * HID + col;
            float4 wa = __ldg((const float4*)(wg));
            float4 wb = __ldg((const float4*)(wg + HID * HID));
            float4 wc = __ldg((const float4*)(wg + 2 * HID * HID));
            u64 wa0 = dup2(wa.x), wa1 = dup2(wa.y), wa2 = dup2(wa.z), wa3 = dup2(wa.w);
            u64 wb0 = dup2(wb.x), wb1 = dup2(wb.y), wb2 = dup2(wb.z), wb3 = dup2(wb.w);
            u64 wc0 = dup2(wc.x), wc1 = dup2(wc.y), wc2 = dup2(wc.z), wc3 = dup2(wc.w);
            const float* serow = t_se  + j * S + rbase;
            const float* smrow = t_m4a + j * S + rbase;
            #pragma unroll
            for (int rp = 0; rp < 4; rp++) {
                u64 se = *(const u64*)(serow + 2 * rp);
                u64 sv = *(const u64*)(smrow + 2 * rp);
                u64 pr = mul2(se, sv);
                acc[rp][0] = fma2(se, wa0, acc[rp][0]);
                acc[rp][1] = fma2(se, wa1, acc[rp][1]);
                acc[rp][2] = fma2(se, wa2, acc[rp][2]);
                acc[rp][3] = fma2(se, wa3, acc[rp][3]);
                acc[rp][0] = fma2(sv, wb0, acc[rp][0]);
                acc[rp][1] = fma2(sv, wb1, acc[rp][1]);
                acc[rp][2] = fma2(sv, wb2, acc[rp][2]);
                acc[rp][3] = fma2(sv, wb3, acc[rp][3]);
                acc[rp][0] = fma2(pr, wc0, acc[rp][0]);
                acc[rp][1] = fma2(pr, wc1, acc[rp][1]);
                acc[rp][2] = fma2(pr, wc2, acc[rp][2]);
                acc[rp][3] = fma2(pr, wc3, acc[rp][3]);
            }
        }
        // epilogue: sigmoid gate + blend, write two rows per row-pair
        #pragma unroll
        for (int rp = 0; rp < 4; rp++) {
            int r0 = rbase + 2 * rp;
            float ge[4], go[4];
            #pragma unroll
            for (int h = 0; h < 4; h++) unpack2(acc[rp][h], ge[h], go[h]);
            float4 oe, oo;
            {
                float se0, se1, sm0, sm1, g;
                #pragma unroll
                for (int h = 0; h < 4; h++) {
                    se0 = t_se [(col + h) * S + r0];
                    se1 = t_se [(col + h) * S + r0 + 1];
                    sm0 = t_m4a[(col + h) * S + r0];
                    sm1 = t_m4a[(col + h) * S + r0 + 1];
                    g = sigmoid_fast(ge[h]);
                    float v0 = se0 + g * (sm0 - se0);
                    g = sigmoid_fast(go[h]);
                    float v1 = se1 + g * (sm1 - se1);
                    ((float*)&oe)[h] = v0;
                    ((float*)&oo)[h] = v1;
                }
            }
            *(float4*)(out + (size_t)(b0 * DOC_L + r0)     * HID + col) = oe;
            *(float4*)(out + (size_t)(b0 * DOC_L + r0 + 1) * HID + col) = oo;
        }
    }
}

extern "C" void kernel_launch(void* const* d_in, const int* in_sizes, int n_in,
                              void* d_out, int out_size)
{
    const float* sub_emb = (const float*)d_in[0];
    const float* memory  = (const float*)d_in[1];
    const int*   sub_len = (const int*)  d_in[2];
    const float* sub_raw = (const float*)d_in[3];
    const float* W_mem   = (const float*)d_in[4];
    const float* b_mem   = (const float*)d_in[5];
    const float* W_sub   = (const float*)d_in[6];
    const float* b_sub   = (const float*)d_in[7];
    const float* W_gate  = (const float*)d_in[8];
    const float* b_gate  = (const float*)d_in[9];
    float* out = (float*)d_out;

    const int B = in_sizes[2];                 // 65536
    // 4 activation buffers (s4a overlays raw) + att + len
    const int smem_bytes = (4 * HID * S + NB * DOC_L * DOC_L + NB) * 4;

    cudaFuncSetAttribute(reading_memory_kernel,
                         cudaFuncAttributeMaxDynamicSharedMemorySize, smem_bytes);

    dim3 grid(B / NB);
    reading_memory_kernel<<<grid, NT, smem_bytes>>>(
        sub_emb, memory, sub_len, sub_raw,
        W_mem, b_mem, W_sub, b_sub, W_gate, b_gate, out);
}

// round 7
// speedup vs baseline: 2.0055x; 1.3757x over previous
#include <cuda_runtime.h>

typedef unsigned long long u64;

#define DOC_L 5
#define HID   100
#define NB    8                 // batches per CTA
#define ROWS  (NB * DOC_L)      // 40
#define S     42                // transposed smem row stride (floats)
#define NT    256

// ---------------- packed f32x2 helpers ----------------
__device__ __forceinline__ u64 fma2(u64 a, u64 b, u64 c) {
    u64 d;
    asm("fma.rn.f32x2 %0, %1, %2, %3;" : "=l"(d) : "l"(a), "l"(b), "l"(c));
    return d;
}
__device__ __forceinline__ u64 mul2(u64 a, u64 b) {
    u64 d;
    asm("mul.rn.f32x2 %0, %1, %2;" : "=l"(d) : "l"(a), "l"(b));
    return d;
}
__device__ __forceinline__ u64 dup2(float a) {
    u64 d;
    asm("mov.b64 %0, {%1, %1};" : "=l"(d) : "f"(a));
    return d;
}
__device__ __forceinline__ void unpack2(u64 v, float& x, float& y) {
    asm("mov.b64 {%0, %1}, %2;" : "=f"(x), "=f"(y) : "l"(v));
}
__device__ __forceinline__ float tanh_fast(float x) {
    return 1.f - 2.f / (__expf(2.f * x) + 1.f);
}
__device__ __forceinline__ float sigmoid_fast(float x) {
    return 1.f / (1.f + __expf(-x));
}

__global__ __launch_bounds__(NT, 3)
void reading_memory_kernel(const float* __restrict__ sub_emb,
                           const float* __restrict__ memory,
                           const int*   __restrict__ sub_len,
                           const float* __restrict__ sub_raw,
                           const float* __restrict__ W_mem,
                           const float* __restrict__ b_mem,
                           const float* __restrict__ W_sub,
                           const float* __restrict__ b_sub,
                           const float* __restrict__ W_gate,
                           const float* __restrict__ b_gate,
                           float* __restrict__ out)
{
    extern __shared__ float sm[];
    // activations TRANSPOSED: [h][row], stride S
    float* t_mem = sm;                  // memory
    float* t_se  = t_mem + HID * S;     // sub_emb
    float* t_raw = t_se  + HID * S;     // sub_emb_raw; aliased to sub_4att after A2
    float* t_s4a = t_raw;               // sub_4att / gate scratch (barrier-protected)
    float* t_m4a = t_raw + HID * S;     // mem_4att, later sub_mem
    float* s_att = t_m4a + HID * S;     // [NB][5][5]
    int*   s_len = (int*)(s_att + NB * DOC_L * DOC_L);

    const int tid = threadIdx.x;
    const int b0  = blockIdx.x * NB;

    const float* g_mem = memory  + (size_t)b0 * DOC_L * HID;
    const float* g_se  = sub_emb + (size_t)b0 * DOC_L * HID;
    const float* g_raw = sub_raw + (size_t)b0 * DOC_L * HID;

    // ---- stage inputs transposed ----
    for (int i = tid; i < ROWS * HID / 4; i += NT) {
        int e = i * 4;
        int r = e / HID;
        int c = e - r * HID;
        float4 vm = *(const float4*)(g_mem + e);
        float4 vs = *(const float4*)(g_se  + e);
        float4 vr = *(const float4*)(g_raw + e);
        t_mem[(c + 0) * S + r] = vm.x; t_mem[(c + 1) * S + r] = vm.y;
        t_mem[(c + 2) * S + r] = vm.z; t_mem[(c + 3) * S + r] = vm.w;
        t_se [(c + 0) * S + r] = vs.x; t_se [(c + 1) * S + r] = vs.y;
        t_se [(c + 2) * S + r] = vs.z; t_se [(c + 3) * S + r] = vs.w;
        t_raw[(c + 0) * S + r] = vr.x; t_raw[(c + 1) * S + r] = vr.y;
        t_raw[(c + 2) * S + r] = vr.z; t_raw[(c + 3) * S + r] = vr.w;
    }
    if (tid < NB) s_len[tid] = sub_len[b0 + tid];
    __syncthreads();

    const int  lt     = tid % 125;
    const int  half   = tid / 125;       // 0 or 1 (2 for idle tail)
    const bool active = (tid < 250);
    const int  hq     = lt % 25;         // owns cols col..col+3
    const int  rg     = lt / 25;         // row group (8 rows = 4 row-pairs)
    const int  col    = 4 * hq;
    const int  rbase  = rg * 8;

    u64 acc[4][4];                       // [row-pair][h], reused each phase

    // ================= phase A: mem_4att = tanh(memory @ W_mem + b) =================
    if (active) {
        if (half == 0) {
            float4 bb = *(const float4*)(b_mem + col);
            u64 b0d = dup2(bb.x), b1d = dup2(bb.y), b2d = dup2(bb.z), b3d = dup2(bb.w);
            #pragma unroll
            for (int rp = 0; rp < 4; rp++) {
                acc[rp][0] = b0d; acc[rp][1] = b1d; acc[rp][2] = b2d; acc[rp][3] = b3d;
            }
        } else {
            #pragma unroll
            for (int rp = 0; rp < 4; rp++)
                #pragma unroll
                for (int h = 0; h < 4; h++) acc[rp][h] = 0ull;
        }
        const int j0 = half * 50;
        #pragma unroll 2
        for (int j = j0; j < j0 + 50; j++) {
            float4 w = __ldg((const float4*)(W_mem + j * HID + col));
            u64 w0 = dup2(w.x), w1 = dup2(w.y), w2 = dup2(w.z), w3 = dup2(w.w);
            const float* arow = t_mem + j * S + rbase;
            #pragma unroll
            for (int rp = 0; rp < 4; rp++) {
                u64 a = *(const u64*)(arow + 2 * rp);
                acc[rp][0] = fma2(a, w0, acc[rp][0]);
                acc[rp][1] = fma2(a, w1, acc[rp][1]);
                acc[rp][2] = fma2(a, w2, acc[rp][2]);
                acc[rp][3] = fma2(a, w3, acc[rp][3]);
            }
        }
    }
    __syncthreads();
    if (active && half == 1) {          // park partials at final addresses
        #pragma unroll
        for (int rp = 0; rp < 4; rp++)
            #pragma unroll
            for (int h = 0; h < 4; h++) {
                float e, o;
                unpack2(acc[rp][h], e, o);
                *(float2*)(t_m4a + (col + h) * S + rbase + 2 * rp) = make_float2(e, o);
            }
    }
    __syncthreads();
    if (active && half == 0) {          // combine + tanh
        #pragma unroll
        for (int rp = 0; rp < 4; rp++)
            #pragma unroll
            for (int h = 0; h < 4; h++) {
                float* addr = t_m4a + (col + h) * S + rbase + 2 * rp;
                float2 p = *(float2*)addr;
                float e, o;
                unpack2(acc[rp][h], e, o);
                *(float2*)addr = make_float2(tanh_fast(p.x + e), tanh_fast(p.y + o));
            }
    }

    // ========= phase A2: sub_4att = tanh(cat(sub_emb, raw) @ W_sub + b) =========
    // half 0 accumulates sub_emb x W_sub[0:100); half 1 raw x W_sub[100:200)
    if (active) {
        if (half == 0) {
            float4 bb = *(const float4*)(b_sub + col);
            u64 b0d = dup2(bb.x), b1d = dup2(bb.y), b2d = dup2(bb.z), b3d = dup2(bb.w);
            #pragma unroll
            for (int rp = 0; rp < 4; rp++) {
                acc[rp][0] = b0d; acc[rp][1] = b1d; acc[rp][2] = b2d; acc[rp][3] = b3d;
            }
        } else {
            #pragma unroll
            for (int rp = 0; rp < 4; rp++)
                #pragma unroll
                for (int h = 0; h < 4; h++) acc[rp][h] = 0ull;
        }
        const float* src   = (half == 0) ? t_se : t_raw;
        const float* wbase = W_sub + (half == 0 ? 0 : HID * HID);
        #pragma unroll 2
        for (int j = 0; j < HID; j++) {
            float4 w = __ldg((const float4*)(wbase + j * HID + col));
            u64 w0 = dup2(w.x), w1 = dup2(w.y), w2 = dup2(w.z), w3 = dup2(w.w);
            const float* arow = src + j * S + rbase;
            #pragma unroll
            for (int rp = 0; rp < 4; rp++) {
                u64 a = *(const u64*)(arow + 2 * rp);
                acc[rp][0] = fma2(a, w0, acc[rp][0]);
                acc[rp][1] = fma2(a, w1, acc[rp][1]);
                acc[rp][2] = fma2(a, w2, acc[rp][2]);
                acc[rp][3] = fma2(a, w3, acc[rp][3]);
            }
        }
    }
    __syncthreads();                     // all t_raw reads done; safe to overwrite
    if (active && half == 1) {
        #pragma unroll
        for (int rp = 0; rp < 4; rp++)
            #pragma unroll
            for (int h = 0; h < 4; h++) {
                float e, o;
                unpack2(acc[rp][h], e, o);
                *(float2*)(t_s4a + (col + h) * S + rbase + 2 * rp) = make_float2(e, o);
            }
    }
    __syncthreads();
    if (active && half == 0) {
        #pragma unroll
        for (int rp = 0; rp < 4; rp++)
            #pragma unroll
            for (int h = 0; h < 4; h++) {
                float* addr = t_s4a + (col + h) * S + rbase + 2 * rp;
                float2 p = *(float2*)addr;
                float e, o;
                unpack2(acc[rp][h], e, o);
                *(float2*)addr = make_float2(tanh_fast(p.x + e), tanh_fast(p.y + o));
            }
    }
    __syncthreads();

    // ================= attention scores =================
    for (int p = tid; p < NB * 25; p += NT) {
        int b   = p / 25;
        int rem = p - b * 25;
        int q   = rem / 5;
        int k   = rem - q * 5;
        int rq  = b * DOC_L + q;
        int rk  = b * DOC_L + k;
        float s = 0.f;
        #pragma unroll 4
        for (int j = 0; j < HID; j++)
            s = fmaf(t_s4a[j * S + rq], t_m4a[j * S + rk], s);
        s_att[p] = s;
    }
    __syncthreads();

    // softmax per (b, q); invalid query rows -> zero attention
    if (tid < NB * DOC_L) {
        int b = tid / DOC_L;
        int q = tid - b * DOC_L;
        float* a = s_att + b * 25 + q * 5;
        if (q < s_len[b]) {
            float m = a[0];
            #pragma unroll
            for (int k = 1; k < 5; k++) m = fmaxf(m, a[k]);
            float e[5], s = 0.f;
            #pragma unroll
            for (int k = 0; k < 5; k++) { e[k] = __expf(a[k] - m); s += e[k]; }
            float inv = 1.f / s;
            #pragma unroll
            for (int k = 0; k < 5; k++) a[k] = e[k] * inv;
        } else {
            #pragma unroll
            for (int k = 0; k < 5; k++) a[k] = 0.f;
        }
    }
    __syncthreads();

    // ---- sub_mem = att @ memory (overwrites t_m4a) ----
    for (int idx = tid; idx < HID * ROWS; idx += NT) {
        int h = idx % HID;
        int r = idx / HID;
        int b = r / DOC_L;
        int q = r - b * DOC_L;
        const float* a  = s_att + b * 25 + q * 5;
        const float* mr = t_mem + h * S + b * DOC_L;
        float v = a[0] * mr[0];
        v = fmaf(a[1], mr[1], v);
        v = fmaf(a[2], mr[2], v);
        v = fmaf(a[3], mr[3], v);
        v = fmaf(a[4], mr[4], v);
        t_m4a[h * S + r] = v;
    }
    __syncthreads();

    // ================= gate GEMM (K=300, j-split) + output =================
    if (active) {
        if (half == 0) {
            float4 bb = *(const float4*)(b_gate + col);
            u64 b0d = dup2(bb.x), b1d = dup2(bb.y), b2d = dup2(bb.z), b3d = dup2(bb.w);
            #pragma unroll
            for (int rp = 0; rp < 4; rp++) {
                acc[rp][0] = b0d; acc[rp][1] = b1d; acc[rp][2] = b2d; acc[rp][3] = b3d;
            }
        } else {
            #pragma unroll
            for (int rp = 0; rp < 4; rp++)
                #pragma unroll
                for (int h = 0; h < 4; h++) acc[rp][h] = 0ull;
        }
        const int j0 = half * 50;
        #pragma unroll 2
        for (int j = j0; j < j0 + 50; j++) {
            const float* wg = W_gate + j * HID + col;
            float4 wa = __ldg((const float4*)(wg));
            float4 wb = __ldg((const float4*)(wg + HID * HID));
            float4 wc = __ldg((const float4*)(wg + 2 * HID * HID));
            u64 wa0 = dup2(wa.x), wa1 = dup2(wa.y), wa2 = dup2(wa.z), wa3 = dup2(wa.w);
            u64 wb0 = dup2(wb.x), wb1 = dup2(wb.y), wb2 = dup2(wb.z), wb3 = dup2(wb.w);
            u64 wc0 = dup2(wc.x), wc1 = dup2(wc.y), wc2 = dup2(wc.z), wc3 = dup2(wc.w);
            const float* serow = t_se  + j * S + rbase;
            const float* smrow = t_m4a + j * S + rbase;
            #pragma unroll
            for (int rp = 0; rp < 4; rp++) {
                u64 se = *(const u64*)(serow + 2 * rp);
                u64 sv = *(const u64*)(smrow + 2 * rp);
                u64 pr = mul2(se, sv);
                acc[rp][0] = fma2(se, wa0, acc[rp][0]);
                acc[rp][1] = fma2(se, wa1, acc[rp][1]);
                acc[rp][2] = fma2(se, wa2, acc[rp][2]);
                acc[rp][3] = fma2(se, wa3, acc[rp][3]);
                acc[rp][0] = fma2(sv, wb0, acc[rp][0]);
                acc[rp][1] = fma2(sv, wb1, acc[rp][1]);
                acc[rp][2] = fma2(sv, wb2, acc[rp][2]);
                acc[rp][3] = fma2(sv, wb3, acc[rp][3]);
                acc[rp][0] = fma2(pr, wc0, acc[rp][0]);
                acc[rp][1] = fma2(pr, wc1, acc[rp][1]);
                acc[rp][2] = fma2(pr, wc2, acc[rp][2]);
                acc[rp][3] = fma2(pr, wc3, acc[rp][3]);
            }
        }
    }
    __syncthreads();
    if (active && half == 1) {          // park gate partials in dead s4a region
        #pragma unroll
        for (int rp = 0; rp < 4; rp++)
            #pragma unroll
            for (int h = 0; h < 4; h++) {
                float e, o;
                unpack2(acc[rp][h], e, o);
                *(float2*)(t_s4a + (col + h) * S + rbase + 2 * rp) = make_float2(e, o);
            }
    }
    __syncthreads();
    if (active && half == 0) {          // combine + sigmoid + blend + store
        #pragma unroll
        for (int rp = 0; rp < 4; rp++) {
            int r0 = rbase + 2 * rp;
            float4 oe, oo;
            #pragma unroll
            for (int h = 0; h < 4; h++) {
                float2 p = *(float2*)(t_s4a + (col + h) * S + r0);
                float e, o;
                unpack2(acc[rp][h], e, o);
                float g0 = sigmoid_fast(p.x + e);
                float g1 = sigmoid_fast(p.y + o);
                float se0 = t_se [(col + h) * S + r0];
                float se1 = t_se [(col + h) * S + r0 + 1];
                float sm0 = t_m4a[(col + h) * S + r0];
                float sm1 = t_m4a[(col + h) * S + r0 + 1];
                ((float*)&oe)[h] = se0 + g0 * (sm0 - se0);
                ((float*)&oo)[h] = se1 + g1 * (sm1 - se1);
            }
            *(float4*)(out + (size_t)(b0 * DOC_L + r0)     * HID + col) = oe;
            *(float4*)(out + (size_t)(b0 * DOC_L + r0 + 1) * HID + col) = oo;
        }
    }
}

extern "C" void kernel_launch(void* const* d_in, const int* in_sizes, int n_in,
                              void* d_out, int out_size)
{
    const float* sub_emb = (const float*)d_in[0];
    const float* memory  = (const float*)d_in[1];
    const int*   sub_len = (const int*)  d_in[2];
    const float* sub_raw = (const float*)d_in[3];
    const float* W_mem   = (const float*)d_in[4];
    const float* b_mem   = (const float*)d_in[5];
    const float* W_sub   = (const float*)d_in[6];
    const float* b_sub   = (const float*)d_in[7];
    const float* W_gate  = (const float*)d_in[8];
    const float* b_gate  = (const float*)d_in[9];
    float* out = (float*)d_out;

    const int B = in_sizes[2];                 // 65536
    // 4 activation buffers (s4a overlays raw) + att + len
    const int smem_bytes = (4 * HID * S + NB * DOC_L * DOC_L + NB) * 4;

    cudaFuncSetAttribute(reading_memory_kernel,
                         cudaFuncAttributeMaxDynamicSharedMemorySize, smem_bytes);

    dim3 grid(B / NB);
    reading_memory_kernel<<<grid, NT, smem_bytes>>>(
        sub_emb, memory, sub_len, sub_raw,
        W_mem, b_mem, W_sub, b_sub, W_gate, b_gate, out);
}